// round 4
// baseline (speedup 1.0000x reference)
#include <cuda_runtime.h>

// RMSD quaternion loss: B=4096 batches, N=2048 atoms, 3 coords.
// k1: per-batch reduction of R (3x3 cross-correlation) + squared norms. HBM-bound: 201 MB read.
//     Loads issued per-chunk (MLP_p1=6, not 12) to avoid cross-CTA L1tex-queue spread;
//     launch_bounds caps regs at 32 -> 8 blocks/SM.
// k2: per-batch largest eigenvalue of quaternion F via FP64 Newton on the characteristic
//     quartic from the upper bound 2*sqrt(S) >= lmax; fused final reduction via
//     last-block-done counter (reset in-kernel -> graph-replay safe, serial sum -> deterministic).

constexpr int BATCHES = 4096;
constexpr int NATOMS  = 2048;
constexpr int F4_PER_BATCH = NATOMS * 3 / 4;   // 1536 float4 per batch per tensor
constexpr int CHUNKS = NATOMS / 4;             // 512 chunks of 4 atoms (48 B each)
constexpr int K1_THREADS = 256;
constexpr int K2_THREADS = 128;
constexpr int K2_BLOCKS  = BATCHES / K2_THREADS; // 32

// scratch: SoA [10][BATCHES]: r00 r01 r02 r10 r11 r12 r20 r21 r22 sqn
__device__ float        g_scr[10 * BATCHES];
__device__ double       g_part[K2_BLOCKS];
__device__ unsigned int g_done = 0;

__global__ __launch_bounds__(K1_THREADS, 8)
void k1_reduce(const float4* __restrict__ yp, const float4* __restrict__ yy)
{
    const int b = blockIdx.x;
    const float4* __restrict__ yp_b = yp + (size_t)b * F4_PER_BATCH;
    const float4* __restrict__ yy_b = yy + (size_t)b * F4_PER_BATCH;

    float acc[10];
#pragma unroll
    for (int i = 0; i < 10; ++i) acc[i] = 0.0f;

    // 512 chunks / 256 threads = 2 iterations. unroll 1 keeps the LDG burst at 6
    // per iteration (lower MLP_p1 -> less cross-CTA L1tex-queue spread).
#pragma unroll 1
    for (int c = threadIdx.x; c < CHUNKS; c += K1_THREADS) {
        const float4 a0 = yp_b[c * 3 + 0];
        const float4 a1 = yp_b[c * 3 + 1];
        const float4 a2 = yp_b[c * 3 + 2];
        const float4 b0 = yy_b[c * 3 + 0];
        const float4 b1 = yy_b[c * 3 + 1];
        const float4 b2 = yy_b[c * 3 + 2];

        const float px[4] = { a0.x, a0.w, a1.z, a2.y };
        const float py[4] = { a0.y, a1.x, a1.w, a2.z };
        const float pz[4] = { a0.z, a1.y, a2.x, a2.w };
        const float qx[4] = { b0.x, b0.w, b1.z, b2.y };
        const float qy[4] = { b0.y, b1.x, b1.w, b2.z };
        const float qz[4] = { b0.z, b1.y, b2.x, b2.w };

#pragma unroll
        for (int i = 0; i < 4; ++i) {
            acc[0] = fmaf(px[i], qx[i], acc[0]);
            acc[1] = fmaf(px[i], qy[i], acc[1]);
            acc[2] = fmaf(px[i], qz[i], acc[2]);
            acc[3] = fmaf(py[i], qx[i], acc[3]);
            acc[4] = fmaf(py[i], qy[i], acc[4]);
            acc[5] = fmaf(py[i], qz[i], acc[5]);
            acc[6] = fmaf(pz[i], qx[i], acc[6]);
            acc[7] = fmaf(pz[i], qy[i], acc[7]);
            acc[8] = fmaf(pz[i], qz[i], acc[8]);
            acc[9] = fmaf(px[i], px[i], acc[9]);
            acc[9] = fmaf(py[i], py[i], acc[9]);
            acc[9] = fmaf(pz[i], pz[i], acc[9]);
            acc[9] = fmaf(qx[i], qx[i], acc[9]);
            acc[9] = fmaf(qy[i], qy[i], acc[9]);
            acc[9] = fmaf(qz[i], qz[i], acc[9]);
        }
    }

    // warp reduce all 10
#pragma unroll
    for (int i = 0; i < 10; ++i)
#pragma unroll
        for (int off = 16; off > 0; off >>= 1)
            acc[i] += __shfl_down_sync(0xffffffffu, acc[i], off);

    __shared__ float sm[K1_THREADS / 32][10];
    const int warp = threadIdx.x >> 5;
    const int lane = threadIdx.x & 31;
    if (lane == 0) {
#pragma unroll
        for (int i = 0; i < 10; ++i) sm[warp][i] = acc[i];
    }
    __syncthreads();

    if (warp == 0) {
        float v[10];
#pragma unroll
        for (int i = 0; i < 10; ++i)
            v[i] = (lane < (K1_THREADS / 32)) ? sm[lane][i] : 0.0f;
#pragma unroll
        for (int i = 0; i < 10; ++i)
#pragma unroll
            for (int off = (K1_THREADS / 64); off > 0; off >>= 1)
                v[i] += __shfl_down_sync(0xffffffffu, v[i], off);
        if (lane == 0) {
#pragma unroll
            for (int i = 0; i < 10; ++i)
                g_scr[i * BATCHES + b] = v[i];
        }
    }
}

__device__ __forceinline__ double det3(double a, double b, double c,
                                       double d, double e, double f,
                                       double g, double h, double i)
{
    return a * (e * i - f * h) - b * (d * i - f * g) + c * (d * h - e * g);
}

__global__ __launch_bounds__(K2_THREADS)
void k2_eigen_final(float* __restrict__ out)
{
    const int b = blockIdx.x * K2_THREADS + threadIdx.x;

    const double r00 = g_scr[0 * BATCHES + b];
    const double r01 = g_scr[1 * BATCHES + b];
    const double r02 = g_scr[2 * BATCHES + b];
    const double r10 = g_scr[3 * BATCHES + b];
    const double r11 = g_scr[4 * BATCHES + b];
    const double r12 = g_scr[5 * BATCHES + b];
    const double r20 = g_scr[6 * BATCHES + b];
    const double r21 = g_scr[7 * BATCHES + b];
    const double r22 = g_scr[8 * BATCHES + b];
    const double sqn = g_scr[9 * BATCHES + b];

    const double S = r00*r00 + r01*r01 + r02*r02
                   + r10*r10 + r11*r11 + r12*r12
                   + r20*r20 + r21*r21 + r22*r22;
    const double c2 = -2.0 * S;
    const double detR = r00 * (r11 * r22 - r12 * r21)
                      - r01 * (r10 * r22 - r12 * r20)
                      + r02 * (r10 * r21 - r11 * r20);
    const double c1 = -8.0 * detR;

    // Quaternion key matrix F (symmetric, trace 0)
    const double F00 =  r00 + r11 + r22;
    const double F01 =  r12 - r21;
    const double F02 =  r20 - r02;
    const double F03 =  r01 - r10;
    const double F11 =  r00 - r11 - r22;
    const double F12 =  r01 + r10;
    const double F13 =  r02 + r20;
    const double F22 = -r00 + r11 - r22;
    const double F23 =  r12 + r21;
    const double F33 = -r00 - r11 + r22;

    // c0 = det(F): cofactor expansion along row 0 (symmetric F)
    const double M00 = det3(F11, F12, F13,  F12, F22, F23,  F13, F23, F33);
    const double M01 = det3(F01, F12, F13,  F02, F22, F23,  F03, F23, F33);
    const double M02 = det3(F01, F11, F13,  F02, F12, F23,  F03, F13, F33);
    const double M03 = det3(F01, F11, F12,  F02, F12, F22,  F03, F13, F23);
    const double c0 = F00 * M00 - F01 * M01 + F02 * M02 - F03 * M03;

    // Newton on P(l) = l^4 + c2 l^2 + c1 l + c0 from upper bound l0 = 2*sqrt(S) >= lmax.
    double lam = 2.0 * sqrt(S);
#pragma unroll 1
    for (int it = 0; it < 50; ++it) {
        const double l2 = lam * lam;
        const double p  = ((l2 + c2) * lam + c1) * lam + c0;
        const double dp = (4.0 * l2 + 2.0 * c2) * lam + c1;
        if (fabs(dp) < 1e-300) break;
        const double step = p / dp;
        lam -= step;
        if (fabs(step) < 1e-10 * fabs(lam) + 1e-14) break;
    }

    double sd = sqn - 2.0 * lam;

    // deterministic block tree reduce
    __shared__ double sdata[K2_THREADS];
    sdata[threadIdx.x] = sd;
    __syncthreads();
#pragma unroll
    for (int st = K2_THREADS / 2; st > 0; st >>= 1) {
        if (threadIdx.x < st) sdata[threadIdx.x] += sdata[threadIdx.x + st];
        __syncthreads();
    }

    // fused finalization: last block to finish sums the 32 partials serially
    // (deterministic order) and writes the scalar. Counter reset -> replay-safe.
    if (threadIdx.x == 0) {
        g_part[blockIdx.x] = sdata[0];
        __threadfence();
        const unsigned int t = atomicAdd(&g_done, 1u);
        if (t == K2_BLOCKS - 1) {
            double total = 0.0;
#pragma unroll 1
            for (int i = 0; i < K2_BLOCKS; ++i) total += g_part[i];
            out[0] = (float)sqrt(total / (double)NATOMS);
            g_done = 0;  // reset for next graph replay
            __threadfence();
        }
    }
}

extern "C" void kernel_launch(void* const* d_in, const int* in_sizes, int n_in,
                              void* d_out, int out_size)
{
    const float4* yp = (const float4*)d_in[0]; // y_prime (B, N, 3)
    const float4* yy = (const float4*)d_in[1]; // y       (B, N, 3)
    float* out = (float*)d_out;

    k1_reduce<<<BATCHES, K1_THREADS>>>(yp, yy);
    k2_eigen_final<<<K2_BLOCKS, K2_THREADS>>>(out);
}

// round 5
// speedup vs baseline: 1.0143x; 1.0143x over previous
#include <cuda_runtime.h>

// RMSD quaternion loss: B=4096 batches, N=2048 atoms, 3 coords.
// k1: per-batch reduction of R (3x3 cross-correlation) + squared norms. HBM-bound: 201 MB read.
//     Loads issued per-chunk (MLP_p1=6), launch_bounds(256,8) -> 8 blocks/SM.
// k2: 128 blocks x 32 threads (1 batch/thread) -> FP64 Newton spread over 128 SMs.
//     Fused finalization: last-done block's WARP loads the 128 partials in parallel
//     (fixed order -> deterministic) and writes the scalar. Counter reset -> replay-safe.

constexpr int BATCHES = 4096;
constexpr int NATOMS  = 2048;
constexpr int F4_PER_BATCH = NATOMS * 3 / 4;   // 1536 float4 per batch per tensor
constexpr int CHUNKS = NATOMS / 4;             // 512 chunks of 4 atoms (48 B each)
constexpr int K1_THREADS = 256;
constexpr int K2_THREADS = 32;
constexpr int K2_BLOCKS  = BATCHES / K2_THREADS; // 128

// scratch: SoA [10][BATCHES]: r00 r01 r02 r10 r11 r12 r20 r21 r22 sqn
__device__ float        g_scr[10 * BATCHES];
__device__ double       g_part[K2_BLOCKS];
__device__ unsigned int g_done = 0;

__global__ __launch_bounds__(K1_THREADS, 8)
void k1_reduce(const float4* __restrict__ yp, const float4* __restrict__ yy)
{
    const int b = blockIdx.x;
    const float4* __restrict__ yp_b = yp + (size_t)b * F4_PER_BATCH;
    const float4* __restrict__ yy_b = yy + (size_t)b * F4_PER_BATCH;

    float acc[10];
#pragma unroll
    for (int i = 0; i < 10; ++i) acc[i] = 0.0f;

#pragma unroll 1
    for (int c = threadIdx.x; c < CHUNKS; c += K1_THREADS) {
        const float4 a0 = yp_b[c * 3 + 0];
        const float4 a1 = yp_b[c * 3 + 1];
        const float4 a2 = yp_b[c * 3 + 2];
        const float4 b0 = yy_b[c * 3 + 0];
        const float4 b1 = yy_b[c * 3 + 1];
        const float4 b2 = yy_b[c * 3 + 2];

        const float px[4] = { a0.x, a0.w, a1.z, a2.y };
        const float py[4] = { a0.y, a1.x, a1.w, a2.z };
        const float pz[4] = { a0.z, a1.y, a2.x, a2.w };
        const float qx[4] = { b0.x, b0.w, b1.z, b2.y };
        const float qy[4] = { b0.y, b1.x, b1.w, b2.z };
        const float qz[4] = { b0.z, b1.y, b2.x, b2.w };

#pragma unroll
        for (int i = 0; i < 4; ++i) {
            acc[0] = fmaf(px[i], qx[i], acc[0]);
            acc[1] = fmaf(px[i], qy[i], acc[1]);
            acc[2] = fmaf(px[i], qz[i], acc[2]);
            acc[3] = fmaf(py[i], qx[i], acc[3]);
            acc[4] = fmaf(py[i], qy[i], acc[4]);
            acc[5] = fmaf(py[i], qz[i], acc[5]);
            acc[6] = fmaf(pz[i], qx[i], acc[6]);
            acc[7] = fmaf(pz[i], qy[i], acc[7]);
            acc[8] = fmaf(pz[i], qz[i], acc[8]);
            acc[9] = fmaf(px[i], px[i], acc[9]);
            acc[9] = fmaf(py[i], py[i], acc[9]);
            acc[9] = fmaf(pz[i], pz[i], acc[9]);
            acc[9] = fmaf(qx[i], qx[i], acc[9]);
            acc[9] = fmaf(qy[i], qy[i], acc[9]);
            acc[9] = fmaf(qz[i], qz[i], acc[9]);
        }
    }

    // warp reduce all 10
#pragma unroll
    for (int i = 0; i < 10; ++i)
#pragma unroll
        for (int off = 16; off > 0; off >>= 1)
            acc[i] += __shfl_down_sync(0xffffffffu, acc[i], off);

    __shared__ float sm[K1_THREADS / 32][10];
    const int warp = threadIdx.x >> 5;
    const int lane = threadIdx.x & 31;
    if (lane == 0) {
#pragma unroll
        for (int i = 0; i < 10; ++i) sm[warp][i] = acc[i];
    }
    __syncthreads();

    if (warp == 0) {
        float v[10];
#pragma unroll
        for (int i = 0; i < 10; ++i)
            v[i] = (lane < (K1_THREADS / 32)) ? sm[lane][i] : 0.0f;
#pragma unroll
        for (int i = 0; i < 10; ++i)
#pragma unroll
            for (int off = (K1_THREADS / 64); off > 0; off >>= 1)
                v[i] += __shfl_down_sync(0xffffffffu, v[i], off);
        if (lane == 0) {
#pragma unroll
            for (int i = 0; i < 10; ++i)
                g_scr[i * BATCHES + b] = v[i];
        }
    }
}

__device__ __forceinline__ double det3(double a, double b, double c,
                                       double d, double e, double f,
                                       double g, double h, double i)
{
    return a * (e * i - f * h) - b * (d * i - f * g) + c * (d * h - e * g);
}

__global__ __launch_bounds__(K2_THREADS)
void k2_eigen_final(float* __restrict__ out)
{
    const int lane = threadIdx.x;
    const int b = blockIdx.x * K2_THREADS + lane;

    const double r00 = g_scr[0 * BATCHES + b];
    const double r01 = g_scr[1 * BATCHES + b];
    const double r02 = g_scr[2 * BATCHES + b];
    const double r10 = g_scr[3 * BATCHES + b];
    const double r11 = g_scr[4 * BATCHES + b];
    const double r12 = g_scr[5 * BATCHES + b];
    const double r20 = g_scr[6 * BATCHES + b];
    const double r21 = g_scr[7 * BATCHES + b];
    const double r22 = g_scr[8 * BATCHES + b];
    const double sqn = g_scr[9 * BATCHES + b];

    const double S = r00*r00 + r01*r01 + r02*r02
                   + r10*r10 + r11*r11 + r12*r12
                   + r20*r20 + r21*r21 + r22*r22;
    const double c2 = -2.0 * S;
    const double detR = r00 * (r11 * r22 - r12 * r21)
                      - r01 * (r10 * r22 - r12 * r20)
                      + r02 * (r10 * r21 - r11 * r20);
    const double c1 = -8.0 * detR;

    // Quaternion key matrix F (symmetric, trace 0)
    const double F00 =  r00 + r11 + r22;
    const double F01 =  r12 - r21;
    const double F02 =  r20 - r02;
    const double F03 =  r01 - r10;
    const double F11 =  r00 - r11 - r22;
    const double F12 =  r01 + r10;
    const double F13 =  r02 + r20;
    const double F22 = -r00 + r11 - r22;
    const double F23 =  r12 + r21;
    const double F33 = -r00 - r11 + r22;

    // c0 = det(F): cofactor expansion along row 0 (symmetric F)
    const double M00 = det3(F11, F12, F13,  F12, F22, F23,  F13, F23, F33);
    const double M01 = det3(F01, F12, F13,  F02, F22, F23,  F03, F23, F33);
    const double M02 = det3(F01, F11, F13,  F02, F12, F23,  F03, F13, F33);
    const double M03 = det3(F01, F11, F12,  F02, F12, F22,  F03, F13, F23);
    const double c0 = F00 * M00 - F01 * M01 + F02 * M02 - F03 * M03;

    // Newton on P(l) = l^4 + c2 l^2 + c1 l + c0 from upper bound l0 = 2*sqrt(S) >= lmax.
    double lam = 2.0 * sqrt(S);
#pragma unroll 1
    for (int it = 0; it < 30; ++it) {
        const double l2 = lam * lam;
        const double p  = ((l2 + c2) * lam + c1) * lam + c0;
        const double dp = (4.0 * l2 + 2.0 * c2) * lam + c1;
        if (fabs(dp) < 1e-300) break;
        const double step = p / dp;
        lam -= step;
        if (fabs(step) < 1e-9 * fabs(lam) + 1e-14) break;
    }

    double sd = sqn - 2.0 * lam;

    // deterministic warp tree reduce
#pragma unroll
    for (int off = 16; off > 0; off >>= 1)
        sd += __shfl_down_sync(0xffffffffu, sd, off);

    // publish partial; last-done block finalizes with its whole warp
    unsigned int t = 0;
    if (lane == 0) {
        g_part[blockIdx.x] = sd;
        __threadfence();
        t = atomicAdd(&g_done, 1u);
    }
    t = __shfl_sync(0xffffffffu, t, 0);

    if (t == K2_BLOCKS - 1) {
        __threadfence();  // acquire: make all g_part writes visible
        // lane k sums g_part[k], g_part[k+32], g_part[k+64], g_part[k+96] (fixed order)
        double v = 0.0;
#pragma unroll
        for (int j = 0; j < K2_BLOCKS / 32; ++j)
            v += __ldcg(&g_part[lane + 32 * j]);
#pragma unroll
        for (int off = 16; off > 0; off >>= 1)
            v += __shfl_down_sync(0xffffffffu, v, off);
        if (lane == 0) {
            out[0] = (float)sqrt(v / (double)NATOMS);
            g_done = 0;  // reset for next graph replay
            __threadfence();
        }
    }
}

extern "C" void kernel_launch(void* const* d_in, const int* in_sizes, int n_in,
                              void* d_out, int out_size)
{
    const float4* yp = (const float4*)d_in[0]; // y_prime (B, N, 3)
    const float4* yy = (const float4*)d_in[1]; // y       (B, N, 3)
    float* out = (float*)d_out;

    k1_reduce<<<BATCHES, K1_THREADS>>>(yp, yy);
    k2_eigen_final<<<K2_BLOCKS, K2_THREADS>>>(out);
}